// round 2
// baseline (speedup 1.0000x reference)
#include <cuda_runtime.h>
#include <cuda_bf16.h>
#include <cstdint>

// ---------------------------------------------------------------------------
// GATEncoder: 3 layers of (GATConv + linear skip + ELU)
// N=50000, E=800000 (+N self loops), IN=128, H=4, C=64, HC=256
// NOTE: edge_index is int32 (JAX x64 disabled downgrades int64 -> int32).
// ---------------------------------------------------------------------------

#define NNODES 50000
#define NEDGES 800000
#define ETOT   (NEDGES + NNODES)
#define HC     256

// ------------------------- static device scratch ---------------------------
__device__ float g_h  [(size_t)NNODES * HC];   // x @ W           (per layer)
__device__ float g_acc[(size_t)NNODES * HC];   // skip + b, then += messages
__device__ float g_x  [(size_t)NNODES * HC];   // layer intermediate activations
__device__ float g_s  [(size_t)NNODES * 4];
__device__ float g_d  [(size_t)NNODES * 4];
__device__ int   g_m  [(size_t)NNODES * 4];    // ordered-int float max
__device__ float g_den[(size_t)NNODES * 4];
__device__ float g_ex [(size_t)ETOT  * 4];     // per-edge e, then exp(e-m)

// ------------------------- helpers ----------------------------------------
__device__ __forceinline__ int f2o(float f) {
    int i = __float_as_int(f);
    return i >= 0 ? i : (i ^ 0x7FFFFFFF);
}
__device__ __forceinline__ float o2f(int i) {
    return __int_as_float(i >= 0 ? i : (i ^ 0x7FFFFFFF));
}
__device__ __forceinline__ float lrelu(float v) {
    return v > 0.f ? v : 0.2f * v;
}

// ------------------------- GEMM: C[M,256] = A[M,K] @ B[K,256] (+bias) ------
// BM=BN=64, BK=16, 16x16 threads, 4x4 per thread
__global__ void gemm_kernel(const float* __restrict__ A,
                            const float* __restrict__ B,
                            float* __restrict__ C,
                            const float* __restrict__ bias_a,
                            const float* __restrict__ bias_b,
                            int M, int K) {
    __shared__ float As[16][64];
    __shared__ float Bs[16][64];

    const int m0 = blockIdx.y * 64;
    const int n0 = blockIdx.x * 64;
    const int tid = threadIdx.y * 16 + threadIdx.x;

    // A tile loader: 64 rows x 16 cols, float4 per thread
    const int aRow = tid >> 2;
    const int aCol = (tid & 3) * 4;
    // B tile loader: 16 rows x 64 cols, float4 per thread
    const int bRow = tid >> 4;
    const int bCol = (tid & 15) * 4;

    float acc[4][4];
#pragma unroll
    for (int i = 0; i < 4; i++)
#pragma unroll
        for (int j = 0; j < 4; j++) acc[i][j] = 0.f;

    for (int k0 = 0; k0 < K; k0 += 16) {
        float4 av = make_float4(0.f, 0.f, 0.f, 0.f);
        if (m0 + aRow < M)
            av = *(const float4*)&A[(size_t)(m0 + aRow) * K + k0 + aCol];
        As[aCol + 0][aRow] = av.x;
        As[aCol + 1][aRow] = av.y;
        As[aCol + 2][aRow] = av.z;
        As[aCol + 3][aRow] = av.w;

        float4 bv = *(const float4*)&B[(size_t)(k0 + bRow) * HC + n0 + bCol];
        *(float4*)&Bs[bRow][bCol] = bv;

        __syncthreads();
#pragma unroll
        for (int k = 0; k < 16; k++) {
            float ra[4], rb[4];
#pragma unroll
            for (int i = 0; i < 4; i++) ra[i] = As[k][threadIdx.y * 4 + i];
#pragma unroll
            for (int j = 0; j < 4; j++) rb[j] = Bs[k][threadIdx.x * 4 + j];
#pragma unroll
            for (int i = 0; i < 4; i++)
#pragma unroll
                for (int j = 0; j < 4; j++) acc[i][j] = fmaf(ra[i], rb[j], acc[i][j]);
        }
        __syncthreads();
    }

#pragma unroll
    for (int i = 0; i < 4; i++) {
        const int m = m0 + threadIdx.y * 4 + i;
        if (m >= M) continue;
#pragma unroll
        for (int j = 0; j < 4; j++) {
            const int n = n0 + threadIdx.x * 4 + j;
            float bsum = 0.f;
            if (bias_a) bsum += bias_a[n];
            if (bias_b) bsum += bias_b[n];
            C[(size_t)m * HC + n] = acc[i][j] + bsum;
        }
    }
}

// ------------------------- s/d per node + init m/den -----------------------
// one warp per node
__global__ void compute_sd_kernel(const float* __restrict__ gh,
                                  const float* __restrict__ a_src,
                                  const float* __restrict__ a_dst,
                                  float* __restrict__ gs, float* __restrict__ gd,
                                  int* __restrict__ gm, float* __restrict__ gden,
                                  int n_nodes) {
    const int warp = (blockIdx.x * blockDim.x + threadIdx.x) >> 5;
    const int lane = threadIdx.x & 31;
    if (warp >= n_nodes) return;
    const float* hr = gh + (size_t)warp * HC;
#pragma unroll
    for (int h = 0; h < 4; h++) {
        const float h1 = hr[h * 64 + lane];
        const float h2 = hr[h * 64 + 32 + lane];
        float s = h1 * a_src[h * 64 + lane] + h2 * a_src[h * 64 + 32 + lane];
        float d = h1 * a_dst[h * 64 + lane] + h2 * a_dst[h * 64 + 32 + lane];
#pragma unroll
        for (int off = 16; off > 0; off >>= 1) {
            s += __shfl_down_sync(0xFFFFFFFFu, s, off);
            d += __shfl_down_sync(0xFFFFFFFFu, d, off);
        }
        if (lane == 0) {
            gs[warp * 4 + h] = s;
            gd[warp * 4 + h] = d;
            gm[warp * 4 + h] = 0x80000000;  // INT_MIN -> ordered -inf
            gden[warp * 4 + h] = 0.f;
        }
    }
}

// ------------------------- edge pass 1: e + segment max --------------------
__global__ void edge_pass1_kernel(const int* __restrict__ ei,
                                  const float* __restrict__ gs,
                                  const float* __restrict__ gd,
                                  float* __restrict__ gex,
                                  int* __restrict__ gm,
                                  int nE, int nTot) {
    const int e = blockIdx.x * blockDim.x + threadIdx.x;
    if (e >= nTot) return;
    int s, dd;
    if (e < nE) { s = ei[e]; dd = ei[nE + e]; }
    else        { s = dd = e - nE; }

    const float4 sv = ((const float4*)gs)[s];
    const float4 dv = ((const float4*)gd)[dd];
    float4 ev;
    ev.x = lrelu(sv.x + dv.x);
    ev.y = lrelu(sv.y + dv.y);
    ev.z = lrelu(sv.z + dv.z);
    ev.w = lrelu(sv.w + dv.w);
    ((float4*)gex)[e] = ev;

    atomicMax(&gm[dd * 4 + 0], f2o(ev.x));
    atomicMax(&gm[dd * 4 + 1], f2o(ev.y));
    atomicMax(&gm[dd * 4 + 2], f2o(ev.z));
    atomicMax(&gm[dd * 4 + 3], f2o(ev.w));
}

// ------------------------- edge pass 2: exp + segment sum ------------------
__global__ void edge_pass2_kernel(const int* __restrict__ ei,
                                  float* __restrict__ gex,
                                  const int* __restrict__ gm,
                                  float* __restrict__ gden,
                                  int nE, int nTot) {
    const int e = blockIdx.x * blockDim.x + threadIdx.x;
    if (e >= nTot) return;
    int dd;
    if (e < nE) dd = ei[nE + e];
    else        dd = e - nE;

    float4 ev = ((const float4*)gex)[e];
    const int4 mv = ((const int4*)gm)[dd];
    ev.x = expf(ev.x - o2f(mv.x));
    ev.y = expf(ev.y - o2f(mv.y));
    ev.z = expf(ev.z - o2f(mv.z));
    ev.w = expf(ev.w - o2f(mv.w));
    ((float4*)gex)[e] = ev;

    atomicAdd(&gden[dd * 4 + 0], ev.x);
    atomicAdd(&gden[dd * 4 + 1], ev.y);
    atomicAdd(&gden[dd * 4 + 2], ev.z);
    atomicAdd(&gden[dd * 4 + 3], ev.w);
}

// ------------------------- edge pass 3: weighted aggregation ---------------
// one warp per edge; 256 floats per edge as 64 float4 (2 iters of 32 lanes)
__global__ void edge_aggregate_kernel(const int* __restrict__ ei,
                                      const float* __restrict__ gex,
                                      const float* __restrict__ gden,
                                      const float* __restrict__ gh,
                                      float* __restrict__ gacc,
                                      int nE, int nTot) {
    const int e = (blockIdx.x * blockDim.x + threadIdx.x) >> 5;
    const int lane = threadIdx.x & 31;
    if (e >= nTot) return;
    int s, dd;
    if (e < nE) { s = ei[e]; dd = ei[nE + e]; }
    else        { s = dd = e - nE; }

    const float4 exv = ((const float4*)gex)[e];
    const float4 dnv = ((const float4*)gden)[dd];
    float al[4];
    al[0] = exv.x / (dnv.x + 1e-16f);
    al[1] = exv.y / (dnv.y + 1e-16f);
    al[2] = exv.z / (dnv.z + 1e-16f);
    al[3] = exv.w / (dnv.w + 1e-16f);

    const float4* hs = (const float4*)(gh + (size_t)s * HC);
    float* ad = gacc + (size_t)dd * HC;
#pragma unroll
    for (int j = 0; j < 2; j++) {
        const int i4 = j * 32 + lane;     // float4 index 0..63
        const float4 hv = hs[i4];
        const float a = al[i4 >> 4];      // head = (i4*4)/64
        const int c = i4 * 4;
        atomicAdd(&ad[c + 0], hv.x * a);
        atomicAdd(&ad[c + 1], hv.y * a);
        atomicAdd(&ad[c + 2], hv.z * a);
        atomicAdd(&ad[c + 3], hv.w * a);
    }
}

// ------------------------- finalize: ELU -----------------------------------
__global__ void finalize_kernel(const float* __restrict__ gacc,
                                float* __restrict__ xout, int total) {
    const int i = blockIdx.x * blockDim.x + threadIdx.x;
    if (i >= total) return;
    const float v = gacc[i];
    xout[i] = v > 0.f ? v : expm1f(v);
}

// ---------------------------------------------------------------------------
extern "C" void kernel_launch(void* const* d_in, const int* in_sizes, int n_in,
                              void* d_out, int out_size) {
    const float* x0 = (const float*)d_in[0];
    const int* ei = (const int*)d_in[1];
    const int nE = in_sizes[1] / 2;
    const int nN = NNODES;
    const int nTot = nE + nN;

    const float* W[3]    = {(const float*)d_in[2],  (const float*)d_in[8],  (const float*)d_in[14]};
    const float* ASRC[3] = {(const float*)d_in[3],  (const float*)d_in[9],  (const float*)d_in[15]};
    const float* ADST[3] = {(const float*)d_in[4],  (const float*)d_in[10], (const float*)d_in[16]};
    const float* BB[3]   = {(const float*)d_in[5],  (const float*)d_in[11], (const float*)d_in[17]};
    const float* SW[3]   = {(const float*)d_in[6],  (const float*)d_in[12], (const float*)d_in[18]};
    const float* SB[3]   = {(const float*)d_in[7],  (const float*)d_in[13], (const float*)d_in[19]};
    const int FIN[3] = {128, HC, HC};

    float *ph, *pacc, *px, *ps, *pd, *pden, *pex;
    int* pm;
    cudaGetSymbolAddress((void**)&ph,   g_h);
    cudaGetSymbolAddress((void**)&pacc, g_acc);
    cudaGetSymbolAddress((void**)&px,   g_x);
    cudaGetSymbolAddress((void**)&ps,   g_s);
    cudaGetSymbolAddress((void**)&pd,   g_d);
    cudaGetSymbolAddress((void**)&pm,   g_m);
    cudaGetSymbolAddress((void**)&pden, g_den);
    cudaGetSymbolAddress((void**)&pex,  g_ex);

    const dim3 gemmBlock(16, 16);
    const dim3 gemmGrid(HC / 64, (nN + 63) / 64);
    const int eBlocks  = (nTot + 255) / 256;
    const int aggBlocks = (int)(((long long)nTot * 32 + 255) / 256);
    const int finBlocks = (nN * HC + 255) / 256;
    const int sdBlocks  = (nN * 32 + 255) / 256;

    const float* xin = x0;
    for (int l = 0; l < 3; l++) {
        const int K = FIN[l];
        // h = xin @ W
        gemm_kernel<<<gemmGrid, gemmBlock>>>(xin, W[l], ph, nullptr, nullptr, nN, K);
        // acc = xin @ SW + Sb + b   (skip path + conv bias, message sums added on top)
        gemm_kernel<<<gemmGrid, gemmBlock>>>(xin, SW[l], pacc, SB[l], BB[l], nN, K);
        // attention coefficients per node + init segment max/denom
        compute_sd_kernel<<<sdBlocks, 256>>>(ph, ASRC[l], ADST[l], ps, pd, pm, pden, nN);
        // softmax over incoming edges (3 passes)
        edge_pass1_kernel<<<eBlocks, 256>>>(ei, ps, pd, pex, pm, nE, nTot);
        edge_pass2_kernel<<<eBlocks, 256>>>(ei, pex, pm, pden, nE, nTot);
        edge_aggregate_kernel<<<aggBlocks, 256>>>(ei, pex, pden, ph, pacc, nE, nTot);
        // ELU -> next layer input (or final output)
        float* xout = (l == 2) ? (float*)d_out : px;
        finalize_kernel<<<finBlocks, 256>>>(pacc, xout, nN * HC);
        xin = px;
    }
}

// round 3
// speedup vs baseline: 2.2811x; 2.2811x over previous
#include <cuda_runtime.h>
#include <cuda_bf16.h>
#include <cstdint>

// ---------------------------------------------------------------------------
// GATEncoder: 3 layers of (GATConv + linear skip + ELU)
// N=50000, E=800000 (+N self loops), IN=128, H=4, C=64, HC=256
// edge_index is int32.
// Round 3: f32x2-packed 128x128 GEMM + CSR-based atomic-free aggregation.
// ---------------------------------------------------------------------------

#define NNODES 50000
#define NEDGES 800000
#define ETOT   (NEDGES + NNODES)
#define HC     256

// ------------------------- static device scratch ---------------------------
__device__ float g_h   [(size_t)NNODES * HC];   // x @ W
__device__ float g_acc [(size_t)NNODES * HC];   // x @ SW + Sb + b  (skip+bias)
__device__ float g_x   [(size_t)NNODES * HC];   // layer activations
__device__ float g_s   [(size_t)NNODES * 4];
__device__ float g_d   [(size_t)NNODES * 4];
__device__ int   g_deg [NNODES];
__device__ int   g_cur [NNODES];
__device__ int   g_rp  [NNODES + 1];
__device__ int   g_csr [ETOT];                   // src sorted by dst

// ------------------------- helpers ----------------------------------------
__device__ __forceinline__ float lrelu(float v) { return v > 0.f ? v : 0.2f * v; }

__device__ __forceinline__ unsigned long long pk2(float lo, float hi) {
    unsigned long long r;
    asm("mov.b64 %0, {%1, %2};" : "=l"(r) : "f"(lo), "f"(hi));
    return r;
}
__device__ __forceinline__ void fma2(unsigned long long& d,
                                     unsigned long long a,
                                     unsigned long long b) {
    asm("fma.rn.f32x2 %0, %1, %2, %0;" : "+l"(d) : "l"(a), "l"(b));
}
__device__ __forceinline__ void upk2(unsigned long long v, float& lo, float& hi) {
    asm("mov.b64 {%0, %1}, %2;" : "=f"(lo), "=f"(hi) : "l"(v));
}

// ------------------------- GEMM: C[M,256] = A[M,K] @ B[K,256] (+bias) ------
// BM=128, BN=128, BK=16; 256 threads; 8x8 per thread via packed fma.rn.f32x2
__global__ __launch_bounds__(256, 2)
void gemm_kernel(const float* __restrict__ A,
                 const float* __restrict__ B,
                 float* __restrict__ C,
                 const float* __restrict__ bias_a,
                 const float* __restrict__ bias_b,
                 int M, int K) {
    __shared__ float As[16][132];   // transposed, padded stride
    __shared__ float Bs[16][128];

    const int tid = threadIdx.x;
    const int tx = tid & 15;        // col group 0..15  -> cols tx*8..+7
    const int ty = tid >> 4;        // row group 0..15  -> rows ty*8..+7
    const int m0 = blockIdx.y * 128;
    const int n0 = blockIdx.x * 128;

    // A loader: 128 rows x 16 cols; thread -> rows (tid>>2), (tid>>2)+64; col4 = tid&3
    const int ar = tid >> 2;
    const int ac = (tid & 3) * 4;
    // B loader: 16 rows x 128 cols; thread -> rows (tid>>5), (tid>>5)+8; col = (tid&31)*4
    const int br = tid >> 5;
    const int bc = (tid & 31) * 4;

    unsigned long long acc[8][4];
#pragma unroll
    for (int i = 0; i < 8; i++)
#pragma unroll
        for (int j = 0; j < 4; j++) acc[i][j] = 0ull;

    for (int k0 = 0; k0 < K; k0 += 16) {
        float4 a0 = make_float4(0.f, 0.f, 0.f, 0.f);
        float4 a1 = make_float4(0.f, 0.f, 0.f, 0.f);
        if (m0 + ar < M)      a0 = *(const float4*)&A[(size_t)(m0 + ar) * K + k0 + ac];
        if (m0 + ar + 64 < M) a1 = *(const float4*)&A[(size_t)(m0 + ar + 64) * K + k0 + ac];
        const float4 b0 = *(const float4*)&B[(size_t)(k0 + br) * HC + n0 + bc];
        const float4 b1 = *(const float4*)&B[(size_t)(k0 + br + 8) * HC + n0 + bc];

        __syncthreads();
        As[ac + 0][ar] = a0.x;  As[ac + 1][ar] = a0.y;
        As[ac + 2][ar] = a0.z;  As[ac + 3][ar] = a0.w;
        As[ac + 0][ar + 64] = a1.x;  As[ac + 1][ar + 64] = a1.y;
        As[ac + 2][ar + 64] = a1.z;  As[ac + 3][ar + 64] = a1.w;
        *(float4*)&Bs[br][bc] = b0;
        *(float4*)&Bs[br + 8][bc] = b1;
        __syncthreads();

#pragma unroll
        for (int k = 0; k < 16; k++) {
            const float4 ra0 = *(const float4*)&As[k][ty * 8];
            const float4 ra1 = *(const float4*)&As[k][ty * 8 + 4];
            const float4 rb0 = *(const float4*)&Bs[k][tx * 8];
            const float4 rb1 = *(const float4*)&Bs[k][tx * 8 + 4];

            unsigned long long bp[4];
            bp[0] = pk2(rb0.x, rb0.y);
            bp[1] = pk2(rb0.z, rb0.w);
            bp[2] = pk2(rb1.x, rb1.y);
            bp[3] = pk2(rb1.z, rb1.w);

            const float ra[8] = {ra0.x, ra0.y, ra0.z, ra0.w, ra1.x, ra1.y, ra1.z, ra1.w};
#pragma unroll
            for (int i = 0; i < 8; i++) {
                const unsigned long long ap = pk2(ra[i], ra[i]);
#pragma unroll
                for (int j = 0; j < 4; j++) fma2(acc[i][j], ap, bp[j]);
            }
        }
    }

    // bias for this thread's 8 columns
    float bb[8];
#pragma unroll
    for (int j = 0; j < 8; j++) {
        const int n = n0 + tx * 8 + j;
        float s = 0.f;
        if (bias_a) s += bias_a[n];
        if (bias_b) s += bias_b[n];
        bb[j] = s;
    }

#pragma unroll
    for (int i = 0; i < 8; i++) {
        const int m = m0 + ty * 8 + i;
        if (m >= M) continue;
        float o[8];
#pragma unroll
        for (int j = 0; j < 4; j++) upk2(acc[i][j], o[j * 2], o[j * 2 + 1]);
        float4 w0 = make_float4(o[0] + bb[0], o[1] + bb[1], o[2] + bb[2], o[3] + bb[3]);
        float4 w1 = make_float4(o[4] + bb[4], o[5] + bb[5], o[6] + bb[6], o[7] + bb[7]);
        float* cp = &C[(size_t)m * HC + n0 + tx * 8];
        *(float4*)cp = w0;
        *(float4*)(cp + 4) = w1;
    }
}

// ------------------------- CSR build ---------------------------------------
__global__ void hist_kernel(const int* __restrict__ ei, int* __restrict__ deg,
                            int nE, int nTot) {
    const int e = blockIdx.x * blockDim.x + threadIdx.x;
    if (e >= nTot) return;
    const int d = (e < nE) ? ei[nE + e] : (e - nE);
    atomicAdd(&deg[d], 1);
}

__global__ __launch_bounds__(1024)
void scan_kernel(const int* __restrict__ deg, int* __restrict__ rp,
                 int* __restrict__ cur, int n) {
    __shared__ int part[1024];
    const int t = threadIdx.x;
    const int CH = (n + 1023) / 1024;
    const int start = t * CH;
    int s = 0;
    for (int i = 0; i < CH; i++) {
        const int idx = start + i;
        if (idx < n) s += deg[idx];
    }
    part[t] = s;
    __syncthreads();
    for (int off = 1; off < 1024; off <<= 1) {
        int v = (t >= off) ? part[t - off] : 0;
        __syncthreads();
        part[t] += v;
        __syncthreads();
    }
    int base = (t == 0) ? 0 : part[t - 1];
    for (int i = 0; i < CH; i++) {
        const int idx = start + i;
        if (idx < n) {
            rp[idx] = base;
            cur[idx] = base;
            base += deg[idx];
        }
    }
    if (t == 1023) rp[n] = part[1023];
}

__global__ void scatter_kernel(const int* __restrict__ ei, int* __restrict__ cur,
                               int* __restrict__ csr, int nE, int nTot) {
    const int e = blockIdx.x * blockDim.x + threadIdx.x;
    if (e >= nTot) return;
    int s, d;
    if (e < nE) { s = ei[e]; d = ei[nE + e]; }
    else        { s = d = e - nE; }
    const int pos = atomicAdd(&cur[d], 1);
    csr[pos] = s;
}

// ------------------------- s/d per node ------------------------------------
__global__ void compute_sd_kernel(const float* __restrict__ gh,
                                  const float* __restrict__ a_src,
                                  const float* __restrict__ a_dst,
                                  float* __restrict__ gs, float* __restrict__ gd,
                                  int n_nodes) {
    const int warp = (blockIdx.x * blockDim.x + threadIdx.x) >> 5;
    const int lane = threadIdx.x & 31;
    if (warp >= n_nodes) return;
    const float* hr = gh + (size_t)warp * HC;
#pragma unroll
    for (int h = 0; h < 4; h++) {
        const float h1 = hr[h * 64 + lane];
        const float h2 = hr[h * 64 + 32 + lane];
        float s = h1 * a_src[h * 64 + lane] + h2 * a_src[h * 64 + 32 + lane];
        float d = h1 * a_dst[h * 64 + lane] + h2 * a_dst[h * 64 + 32 + lane];
#pragma unroll
        for (int off = 16; off > 0; off >>= 1) {
            s += __shfl_down_sync(0xFFFFFFFFu, s, off);
            d += __shfl_down_sync(0xFFFFFFFFu, d, off);
        }
        if (lane == 0) {
            gs[warp * 4 + h] = s;
            gd[warp * 4 + h] = d;
        }
    }
}

// ------------------------- fused softmax + aggregate + skip + ELU ----------
// one warp per dst node; lane owns 8 channels; head = lane>>3
__global__ __launch_bounds__(256)
void node_agg_kernel(const int* __restrict__ rp, const int* __restrict__ csr,
                     const float* __restrict__ gs, const float* __restrict__ gd,
                     const float* __restrict__ gh, const float* __restrict__ gskip,
                     float* __restrict__ xout, int nN) {
    const int v = (blockIdx.x * blockDim.x + threadIdx.x) >> 5;
    const int lane = threadIdx.x & 31;
    if (v >= nN) return;

    const int b = rp[v];
    const int e = rp[v + 1];
    const float4 dv = ((const float4*)gd)[v];

    // pass 1: per-head max over incoming edges
    float m0 = -1e30f, m1 = -1e30f, m2 = -1e30f, m3 = -1e30f;
    for (int i = b + lane; i < e; i += 32) {
        const float4 sv = ((const float4*)gs)[csr[i]];
        m0 = fmaxf(m0, lrelu(sv.x + dv.x));
        m1 = fmaxf(m1, lrelu(sv.y + dv.y));
        m2 = fmaxf(m2, lrelu(sv.z + dv.z));
        m3 = fmaxf(m3, lrelu(sv.w + dv.w));
    }
#pragma unroll
    for (int off = 16; off > 0; off >>= 1) {
        m0 = fmaxf(m0, __shfl_xor_sync(0xFFFFFFFFu, m0, off));
        m1 = fmaxf(m1, __shfl_xor_sync(0xFFFFFFFFu, m1, off));
        m2 = fmaxf(m2, __shfl_xor_sync(0xFFFFFFFFu, m2, off));
        m3 = fmaxf(m3, __shfl_xor_sync(0xFFFFFFFFu, m3, off));
    }

    // pass 2: denominators
    float n0 = 0.f, n1 = 0.f, n2 = 0.f, n3 = 0.f;
    for (int i = b + lane; i < e; i += 32) {
        const float4 sv = ((const float4*)gs)[csr[i]];
        n0 += expf(lrelu(sv.x + dv.x) - m0);
        n1 += expf(lrelu(sv.y + dv.y) - m1);
        n2 += expf(lrelu(sv.z + dv.z) - m2);
        n3 += expf(lrelu(sv.w + dv.w) - m3);
    }
#pragma unroll
    for (int off = 16; off > 0; off >>= 1) {
        n0 += __shfl_xor_sync(0xFFFFFFFFu, n0, off);
        n1 += __shfl_xor_sync(0xFFFFFFFFu, n1, off);
        n2 += __shfl_xor_sync(0xFFFFFFFFu, n2, off);
        n3 += __shfl_xor_sync(0xFFFFFFFFu, n3, off);
    }

    // per-lane head constants
    const int h = lane >> 3;
    const float dvh  = (h < 2) ? (h == 0 ? dv.x : dv.y) : (h == 2 ? dv.z : dv.w);
    const float mh   = (h < 2) ? (h == 0 ? m0 : m1) : (h == 2 ? m2 : m3);
    const float dnh  = (h < 2) ? (h == 0 ? n0 : n1) : (h == 2 ? n2 : n3);
    const float invh = 1.f / (dnh + 1e-16f);

    // pass 3: gather h[src] * alpha, lane owns channels [lane*8, lane*8+8)
    float4 a0 = make_float4(0.f, 0.f, 0.f, 0.f);
    float4 a1 = make_float4(0.f, 0.f, 0.f, 0.f);
#pragma unroll 2
    for (int i = b; i < e; i++) {
        const int s = csr[i];
        const float sval = gs[s * 4 + h];
        const float al = expf(lrelu(sval + dvh) - mh) * invh;
        const float4* hp = (const float4*)(gh + (size_t)s * HC) + lane * 2;
        const float4 v0 = hp[0];
        const float4 v1 = hp[1];
        a0.x = fmaf(v0.x, al, a0.x);  a0.y = fmaf(v0.y, al, a0.y);
        a0.z = fmaf(v0.z, al, a0.z);  a0.w = fmaf(v0.w, al, a0.w);
        a1.x = fmaf(v1.x, al, a1.x);  a1.y = fmaf(v1.y, al, a1.y);
        a1.z = fmaf(v1.z, al, a1.z);  a1.w = fmaf(v1.w, al, a1.w);
    }

    // skip + ELU + store
    const float4* sp = (const float4*)(gskip + (size_t)v * HC) + lane * 2;
    const float4 s0 = sp[0];
    const float4 s1 = sp[1];
    float4 o0, o1;
    o0.x = a0.x + s0.x;  o0.y = a0.y + s0.y;  o0.z = a0.z + s0.z;  o0.w = a0.w + s0.w;
    o1.x = a1.x + s1.x;  o1.y = a1.y + s1.y;  o1.z = a1.z + s1.z;  o1.w = a1.w + s1.w;
    o0.x = o0.x > 0.f ? o0.x : expm1f(o0.x);
    o0.y = o0.y > 0.f ? o0.y : expm1f(o0.y);
    o0.z = o0.z > 0.f ? o0.z : expm1f(o0.z);
    o0.w = o0.w > 0.f ? o0.w : expm1f(o0.w);
    o1.x = o1.x > 0.f ? o1.x : expm1f(o1.x);
    o1.y = o1.y > 0.f ? o1.y : expm1f(o1.y);
    o1.z = o1.z > 0.f ? o1.z : expm1f(o1.z);
    o1.w = o1.w > 0.f ? o1.w : expm1f(o1.w);
    float4* op = (float4*)(xout + (size_t)v * HC) + lane * 2;
    op[0] = o0;
    op[1] = o1;
}

// ---------------------------------------------------------------------------
extern "C" void kernel_launch(void* const* d_in, const int* in_sizes, int n_in,
                              void* d_out, int out_size) {
    const float* x0 = (const float*)d_in[0];
    const int* ei = (const int*)d_in[1];
    const int nE = in_sizes[1] / 2;
    const int nN = NNODES;
    const int nTot = nE + nN;

    const float* W[3]    = {(const float*)d_in[2],  (const float*)d_in[8],  (const float*)d_in[14]};
    const float* ASRC[3] = {(const float*)d_in[3],  (const float*)d_in[9],  (const float*)d_in[15]};
    const float* ADST[3] = {(const float*)d_in[4],  (const float*)d_in[10], (const float*)d_in[16]};
    const float* BB[3]   = {(const float*)d_in[5],  (const float*)d_in[11], (const float*)d_in[17]};
    const float* SW[3]   = {(const float*)d_in[6],  (const float*)d_in[12], (const float*)d_in[18]};
    const float* SB[3]   = {(const float*)d_in[7],  (const float*)d_in[13], (const float*)d_in[19]};
    const int FIN[3] = {128, HC, HC};

    float *ph, *pacc, *px, *ps, *pd;
    int *pdeg, *pcur, *prp, *pcsr;
    cudaGetSymbolAddress((void**)&ph,   g_h);
    cudaGetSymbolAddress((void**)&pacc, g_acc);
    cudaGetSymbolAddress((void**)&px,   g_x);
    cudaGetSymbolAddress((void**)&ps,   g_s);
    cudaGetSymbolAddress((void**)&pd,   g_d);
    cudaGetSymbolAddress((void**)&pdeg, g_deg);
    cudaGetSymbolAddress((void**)&pcur, g_cur);
    cudaGetSymbolAddress((void**)&prp,  g_rp);
    cudaGetSymbolAddress((void**)&pcsr, g_csr);

    // ---- CSR build (once; reused by all 3 layers) ----
    cudaMemsetAsync(pdeg, 0, NNODES * sizeof(int));
    const int eBlocks = (nTot + 255) / 256;
    hist_kernel<<<eBlocks, 256>>>(ei, pdeg, nE, nTot);
    scan_kernel<<<1, 1024>>>(pdeg, prp, pcur, nN);
    scatter_kernel<<<eBlocks, 256>>>(ei, pcur, pcsr, nE, nTot);

    const dim3 gemmBlock(256);
    const dim3 gemmGrid(HC / 128, (nN + 127) / 128);
    const int sdBlocks  = (nN * 32 + 255) / 256;
    const int aggBlocks = (nN * 32 + 255) / 256;

    const float* xin = x0;
    for (int l = 0; l < 3; l++) {
        const int K = FIN[l];
        gemm_kernel<<<gemmGrid, gemmBlock>>>(xin, W[l], ph, nullptr, nullptr, nN, K);
        gemm_kernel<<<gemmGrid, gemmBlock>>>(xin, SW[l], pacc, SB[l], BB[l], nN, K);
        compute_sd_kernel<<<sdBlocks, 256>>>(ph, ASRC[l], ADST[l], ps, pd, nN);
        float* xout = (l == 2) ? (float*)d_out : px;
        node_agg_kernel<<<aggBlocks, 256>>>(prp, pcsr, ps, pd, ph, pacc, xout, nN);
        xin = px;
    }
}

// round 5
// speedup vs baseline: 3.2176x; 1.4106x over previous
#include <cuda_runtime.h>
#include <cuda_bf16.h>
#include <cstdint>

// ---------------------------------------------------------------------------
// GATEncoder: 3 layers of (GATConv + linear skip + ELU)
// N=50000, E=800000 (+N self loops), IN=128, H=4, C=64, HC=256
// Round 5: mma.sync bf16-split (3 products) fused dual-GEMM
//          + CSR atomic-free aggregation.
// (tcgen05 is NOT available: harness compiles PTX for compute_103, no 'a'.)
// ---------------------------------------------------------------------------

#define NNODES 50000
#define NEDGES 800000
#define ETOT   (NEDGES + NNODES)
#define HC     256

// ------------------------- static device scratch ---------------------------
__device__ float g_h   [(size_t)NNODES * HC];
__device__ float g_acc [(size_t)NNODES * HC];
__device__ float g_x   [(size_t)NNODES * HC];
__device__ float g_s   [(size_t)NNODES * 4];
__device__ float g_d   [(size_t)NNODES * 4];
__device__ int   g_deg [NNODES];
__device__ int   g_cur [NNODES];
__device__ int   g_rp  [NNODES + 1];
__device__ int   g_csr [ETOT];
// pre-transposed bf16-split fused weights: [512 rows, K cols] per layer
// rows [0,256) = W^T, rows [256,512) = SW^T
__device__ __nv_bfloat16 g_bh[3][131072];
__device__ __nv_bfloat16 g_bl[3][131072];

// ------------------------- helpers ----------------------------------------
__device__ __forceinline__ float lrelu(float v) { return v > 0.f ? v : 0.2f * v; }

__device__ __forceinline__ void mma16816(float* d, const uint32_t* a,
                                         uint32_t b0, uint32_t b1) {
    asm volatile(
        "mma.sync.aligned.m16n8k16.row.col.f32.bf16.bf16.f32 "
        "{%0,%1,%2,%3}, {%4,%5,%6,%7}, {%8,%9}, {%0,%1,%2,%3};"
        : "+f"(d[0]), "+f"(d[1]), "+f"(d[2]), "+f"(d[3])
        : "r"(a[0]), "r"(a[1]), "r"(a[2]), "r"(a[3]), "r"(b0), "r"(b1));
}

// ------------------------- weight preconvert -------------------------------
// W [K, 256] fp32 -> hi/lo bf16, transposed to rows [rowoff, rowoff+256) of [512,K]
__global__ void conv_w_kernel(const float* __restrict__ W,
                              __nv_bfloat16* __restrict__ hi,
                              __nv_bfloat16* __restrict__ lo,
                              int K, int rowoff) {
    const int idx = blockIdx.x * blockDim.x + threadIdx.x;
    if (idx >= K * 256) return;
    const int k = idx / 256;
    const int n = idx % 256;
    const float v = W[idx];
    const __nv_bfloat16 h = __float2bfloat16(v);
    const float r = v - __bfloat162float(h);
    hi[(size_t)(rowoff + n) * K + k] = h;
    lo[(size_t)(rowoff + n) * K + k] = __float2bfloat16(r);
}

// ------------------------- fused dual GEMM (mma.sync bf16 split) -----------
// [Ch | Cacc][M,256|256] = A[M,K] @ [W | SW], bias on the acc half.
// CTA tile 128(m) x 128(n of 512); 8 warps, each 64x32; BK=32.
#define SSTR 40   // smem row stride in bf16 (80 bytes): conflict-free frag loads

__global__ __launch_bounds__(256, 2)
void gemm_mma_kernel(const float* __restrict__ A,
                     const __nv_bfloat16* __restrict__ Bh,
                     const __nv_bfloat16* __restrict__ Bl,
                     float* __restrict__ Ch,
                     float* __restrict__ Cacc,
                     const float* __restrict__ bias1,
                     const float* __restrict__ bias2,
                     int M, int K) {
    __shared__ __nv_bfloat16 sAh[128 * SSTR];
    __shared__ __nv_bfloat16 sAl[128 * SSTR];
    __shared__ __nv_bfloat16 sBh[128 * SSTR];
    __shared__ __nv_bfloat16 sBl[128 * SSTR];

    const int tid = threadIdx.x;
    const int wid = tid >> 5;
    const int lane = tid & 31;
    const int qr = lane >> 2;        // 0..7
    const int qc = (lane & 3) * 2;   // 0,2,4,6
    const int warp_m = (wid >> 2) * 64;   // 0 or 64
    const int warp_n = (wid & 3) * 32;    // 0,32,64,96
    const int m0 = blockIdx.y * 128;
    const int n0 = blockIdx.x * 128;      // 0..384 within fused 512

    float d[4][4][4];
#pragma unroll
    for (int mt = 0; mt < 4; mt++)
#pragma unroll
        for (int nt = 0; nt < 4; nt++)
#pragma unroll
            for (int r = 0; r < 4; r++) d[mt][nt][r] = 0.f;

    const int nch = K >> 5;
    for (int ch = 0; ch < nch; ch++) {
        const int k0 = ch << 5;

        // ---- load A tile 128x32 fp32 -> hi/lo bf16 smem ----
#pragma unroll
        for (int i = 0; i < 2; i++) {
            const int s = tid + i * 256;      // 0..511
            const int r = s >> 2;             // row 0..127
            const int c8 = (s & 3) * 8;       // col 0,8,16,24
            float4 f0 = make_float4(0.f, 0.f, 0.f, 0.f);
            float4 f1 = make_float4(0.f, 0.f, 0.f, 0.f);
            if (m0 + r < M) {
                const float* ap = &A[(size_t)(m0 + r) * K + k0 + c8];
                f0 = *(const float4*)ap;
                f1 = *(const float4*)(ap + 4);
            }
            __nv_bfloat162 h0 = __floats2bfloat162_rn(f0.x, f0.y);
            __nv_bfloat162 h1 = __floats2bfloat162_rn(f0.z, f0.w);
            __nv_bfloat162 h2 = __floats2bfloat162_rn(f1.x, f1.y);
            __nv_bfloat162 h3 = __floats2bfloat162_rn(f1.z, f1.w);
            __nv_bfloat162 l0 = __floats2bfloat162_rn(f0.x - __low2float(h0), f0.y - __high2float(h0));
            __nv_bfloat162 l1 = __floats2bfloat162_rn(f0.z - __low2float(h1), f0.w - __high2float(h1));
            __nv_bfloat162 l2 = __floats2bfloat162_rn(f1.x - __low2float(h2), f1.y - __high2float(h2));
            __nv_bfloat162 l3 = __floats2bfloat162_rn(f1.z - __low2float(h3), f1.w - __high2float(h3));
            uint4 uh = make_uint4(*(uint32_t*)&h0, *(uint32_t*)&h1, *(uint32_t*)&h2, *(uint32_t*)&h3);
            uint4 ul = make_uint4(*(uint32_t*)&l0, *(uint32_t*)&l1, *(uint32_t*)&l2, *(uint32_t*)&l3);
            *(uint4*)&sAh[r * SSTR + c8] = uh;
            *(uint4*)&sAl[r * SSTR + c8] = ul;
        }

        // ---- load B tile 128(n)x32(k) bf16 hi/lo ----
        {
            const int n = tid >> 1;                 // 0..127
            const int kh = (tid & 1) * 16;          // 0 or 16
            const size_t goff = (size_t)(n0 + n) * K + k0 + kh;
            const uint4 vh0 = *(const uint4*)&Bh[goff];
            const uint4 vh1 = *(const uint4*)&Bh[goff + 8];
            const uint4 vl0 = *(const uint4*)&Bl[goff];
            const uint4 vl1 = *(const uint4*)&Bl[goff + 8];
            *(uint4*)&sBh[n * SSTR + kh] = vh0;
            *(uint4*)&sBh[n * SSTR + kh + 8] = vh1;
            *(uint4*)&sBl[n * SSTR + kh] = vl0;
            *(uint4*)&sBl[n * SSTR + kh + 8] = vl1;
        }
        __syncthreads();

        // ---- compute: 2 k16-steps ----
#pragma unroll
        for (int ks = 0; ks < 2; ks++) {
            const int kk = ks * 16;
            uint32_t ah[4][4], al[4][4];
#pragma unroll
            for (int mt = 0; mt < 4; mt++) {
                const int r0 = warp_m + mt * 16 + qr;
                ah[mt][0] = *(const uint32_t*)&sAh[r0 * SSTR + kk + qc];
                ah[mt][1] = *(const uint32_t*)&sAh[(r0 + 8) * SSTR + kk + qc];
                ah[mt][2] = *(const uint32_t*)&sAh[r0 * SSTR + kk + 8 + qc];
                ah[mt][3] = *(const uint32_t*)&sAh[(r0 + 8) * SSTR + kk + 8 + qc];
                al[mt][0] = *(const uint32_t*)&sAl[r0 * SSTR + kk + qc];
                al[mt][1] = *(const uint32_t*)&sAl[(r0 + 8) * SSTR + kk + qc];
                al[mt][2] = *(const uint32_t*)&sAl[r0 * SSTR + kk + 8 + qc];
                al[mt][3] = *(const uint32_t*)&sAl[(r0 + 8) * SSTR + kk + 8 + qc];
            }
#pragma unroll
            for (int nt = 0; nt < 4; nt++) {
                const int nr = warp_n + nt * 8 + qr;
                const uint32_t bh0 = *(const uint32_t*)&sBh[nr * SSTR + kk + qc];
                const uint32_t bh1 = *(const uint32_t*)&sBh[nr * SSTR + kk + 8 + qc];
                const uint32_t bl0 = *(const uint32_t*)&sBl[nr * SSTR + kk + qc];
                const uint32_t bl1 = *(const uint32_t*)&sBl[nr * SSTR + kk + 8 + qc];
#pragma unroll
                for (int mt = 0; mt < 4; mt++) {
                    mma16816(d[mt][nt], ah[mt], bh0, bh1);
                    mma16816(d[mt][nt], ah[mt], bl0, bl1);
                    mma16816(d[mt][nt], al[mt], bh0, bh1);
                }
            }
        }
        __syncthreads();
    }

    // ---- epilogue ----
#pragma unroll
    for (int nt = 0; nt < 4; nt++) {
        const int gcol = n0 + warp_n + nt * 8 + qc;   // fused col 0..511
        float* out;
        int col;
        float bv0 = 0.f, bv1 = 0.f;
        if (gcol < 256) {
            out = Ch;  col = gcol;
        } else {
            out = Cacc;  col = gcol - 256;
            bv0 = bias1[col] + bias2[col];
            bv1 = bias1[col + 1] + bias2[col + 1];
        }
#pragma unroll
        for (int mt = 0; mt < 4; mt++) {
            const int r0 = m0 + warp_m + mt * 16 + qr;
            if (r0 < M) {
                float2 v = make_float2(d[mt][nt][0] + bv0, d[mt][nt][1] + bv1);
                *(float2*)&out[(size_t)r0 * HC + col] = v;
            }
            if (r0 + 8 < M) {
                float2 v = make_float2(d[mt][nt][2] + bv0, d[mt][nt][3] + bv1);
                *(float2*)&out[(size_t)(r0 + 8) * HC + col] = v;
            }
        }
    }
}

// ------------------------- CSR build ---------------------------------------
__global__ void hist_kernel(const int* __restrict__ ei, int* __restrict__ deg,
                            int nE, int nTot) {
    const int e = blockIdx.x * blockDim.x + threadIdx.x;
    if (e >= nTot) return;
    const int d = (e < nE) ? ei[nE + e] : (e - nE);
    atomicAdd(&deg[d], 1);
}

__global__ __launch_bounds__(1024)
void scan_kernel(const int* __restrict__ deg, int* __restrict__ rp,
                 int* __restrict__ cur, int n) {
    __shared__ int part[1024];
    const int t = threadIdx.x;
    const int CH = (n + 1023) / 1024;
    const int start = t * CH;
    int s = 0;
    for (int i = 0; i < CH; i++) {
        const int idx = start + i;
        if (idx < n) s += deg[idx];
    }
    part[t] = s;
    __syncthreads();
    for (int off = 1; off < 1024; off <<= 1) {
        int v = (t >= off) ? part[t - off] : 0;
        __syncthreads();
        part[t] += v;
        __syncthreads();
    }
    int base = (t == 0) ? 0 : part[t - 1];
    for (int i = 0; i < CH; i++) {
        const int idx = start + i;
        if (idx < n) {
            rp[idx] = base;
            cur[idx] = base;
            base += deg[idx];
        }
    }
    if (t == 1023) rp[n] = part[1023];
}

__global__ void scatter_kernel(const int* __restrict__ ei, int* __restrict__ cur,
                               int* __restrict__ csr, int nE, int nTot) {
    const int e = blockIdx.x * blockDim.x + threadIdx.x;
    if (e >= nTot) return;
    int s, d;
    if (e < nE) { s = ei[e]; d = ei[nE + e]; }
    else        { s = d = e - nE; }
    const int pos = atomicAdd(&cur[d], 1);
    csr[pos] = s;
}

// ------------------------- s/d per node ------------------------------------
__global__ void compute_sd_kernel(const float* __restrict__ gh,
                                  const float* __restrict__ a_src,
                                  const float* __restrict__ a_dst,
                                  float* __restrict__ gs, float* __restrict__ gd,
                                  int n_nodes) {
    const int warp = (blockIdx.x * blockDim.x + threadIdx.x) >> 5;
    const int lane = threadIdx.x & 31;
    if (warp >= n_nodes) return;
    const float* hr = gh + (size_t)warp * HC;
#pragma unroll
    for (int h = 0; h < 4; h++) {
        const float h1 = hr[h * 64 + lane];
        const float h2 = hr[h * 64 + 32 + lane];
        float s = h1 * a_src[h * 64 + lane] + h2 * a_src[h * 64 + 32 + lane];
        float d = h1 * a_dst[h * 64 + lane] + h2 * a_dst[h * 64 + 32 + lane];
#pragma unroll
        for (int off = 16; off > 0; off >>= 1) {
            s += __shfl_down_sync(0xFFFFFFFFu, s, off);
            d += __shfl_down_sync(0xFFFFFFFFu, d, off);
        }
        if (lane == 0) {
            gs[warp * 4 + h] = s;
            gd[warp * 4 + h] = d;
        }
    }
}

// ------------------------- fused softmax + aggregate + skip + ELU ----------
__global__ __launch_bounds__(256)
void node_agg_kernel(const int* __restrict__ rp, const int* __restrict__ csr,
                     const float* __restrict__ gs, const float* __restrict__ gd,
                     const float* __restrict__ gh, const float* __restrict__ gskip,
                     float* __restrict__ xout, int nN) {
    const int v = (blockIdx.x * blockDim.x + threadIdx.x) >> 5;
    const int lane = threadIdx.x & 31;
    if (v >= nN) return;

    const int b = rp[v];
    const int e = rp[v + 1];
    const float4 dv = ((const float4*)gd)[v];

    float m0 = -1e30f, m1 = -1e30f, m2 = -1e30f, m3 = -1e30f;
    for (int i = b + lane; i < e; i += 32) {
        const float4 sv = ((const float4*)gs)[csr[i]];
        m0 = fmaxf(m0, lrelu(sv.x + dv.x));
        m1 = fmaxf(m1, lrelu(sv.y + dv.y));
        m2 = fmaxf(m2, lrelu(sv.z + dv.z));
        m3 = fmaxf(m3, lrelu(sv.w + dv.w));
    }
#pragma unroll
    for (int off = 16; off > 0; off >>= 1) {
        m0 = fmaxf(m0, __shfl_xor_sync(0xFFFFFFFFu, m0, off));
        m1 = fmaxf(m1, __shfl_xor_sync(0xFFFFFFFFu, m1, off));
        m2 = fmaxf(m2, __shfl_xor_sync(0xFFFFFFFFu, m2, off));
        m3 = fmaxf(m3, __shfl_xor_sync(0xFFFFFFFFu, m3, off));
    }

    float n0 = 0.f, n1 = 0.f, n2 = 0.f, n3 = 0.f;
    for (int i = b + lane; i < e; i += 32) {
        const float4 sv = ((const float4*)gs)[csr[i]];
        n0 += expf(lrelu(sv.x + dv.x) - m0);
        n1 += expf(lrelu(sv.y + dv.y) - m1);
        n2 += expf(lrelu(sv.z + dv.z) - m2);
        n3 += expf(lrelu(sv.w + dv.w) - m3);
    }
#pragma unroll
    for (int off = 16; off > 0; off >>= 1) {
        n0 += __shfl_xor_sync(0xFFFFFFFFu, n0, off);
        n1 += __shfl_xor_sync(0xFFFFFFFFu, n1, off);
        n2 += __shfl_xor_sync(0xFFFFFFFFu, n2, off);
        n3 += __shfl_xor_sync(0xFFFFFFFFu, n3, off);
    }

    const int h = lane >> 3;
    const float dvh  = (h < 2) ? (h == 0 ? dv.x : dv.y) : (h == 2 ? dv.z : dv.w);
    const float mh   = (h < 2) ? (h == 0 ? m0 : m1) : (h == 2 ? m2 : m3);
    const float dnh  = (h < 2) ? (h == 0 ? n0 : n1) : (h == 2 ? n2 : n3);
    const float invh = 1.f / (dnh + 1e-16f);

    float4 a0 = make_float4(0.f, 0.f, 0.f, 0.f);
    float4 a1 = make_float4(0.f, 0.f, 0.f, 0.f);
#pragma unroll 2
    for (int i = b; i < e; i++) {
        const int s = csr[i];
        const float sval = gs[s * 4 + h];
        const float al = expf(lrelu(sval + dvh) - mh) * invh;
        const float4* hp = (const float4*)(gh + (size_t)s * HC) + lane * 2;
        const float4 v0 = hp[0];
        const float4 v1 = hp[1];
        a0.x = fmaf(v0.x, al, a0.x);  a0.y = fmaf(v0.y, al, a0.y);
        a0.z = fmaf(v0.z, al, a0.z);  a0.w = fmaf(v0.w, al, a0.w);
        a1.x = fmaf(v1.x, al, a1.x);  a1.y = fmaf(v1.y, al, a1.y);
        a1.z = fmaf(v1.z, al, a1.z);  a1.w = fmaf(v1.w, al, a1.w);
    }

    const float4* sp = (const float4*)(gskip + (size_t)v * HC) + lane * 2;
    const float4 s0 = sp[0];
    const float4 s1 = sp[1];
    float4 o0, o1;
    o0.x = a0.x + s0.x;  o0.y = a0.y + s0.y;  o0.z = a0.z + s0.z;  o0.w = a0.w + s0.w;
    o1.x = a1.x + s1.x;  o1.y = a1.y + s1.y;  o1.z = a1.z + s1.z;  o1.w = a1.w + s1.w;
    o0.x = o0.x > 0.f ? o0.x : expm1f(o0.x);
    o0.y = o0.y > 0.f ? o0.y : expm1f(o0.y);
    o0.z = o0.z > 0.f ? o0.z : expm1f(o0.z);
    o0.w = o0.w > 0.f ? o0.w : expm1f(o0.w);
    o1.x = o1.x > 0.f ? o1.x : expm1f(o1.x);
    o1.y = o1.y > 0.f ? o1.y : expm1f(o1.y);
    o1.z = o1.z > 0.f ? o1.z : expm1f(o1.z);
    o1.w = o1.w > 0.f ? o1.w : expm1f(o1.w);
    float4* op = (float4*)(xout + (size_t)v * HC) + lane * 2;
    op[0] = o0;
    op[1] = o1;
}

// ---------------------------------------------------------------------------
extern "C" void kernel_launch(void* const* d_in, const int* in_sizes, int n_in,
                              void* d_out, int out_size) {
    const float* x0 = (const float*)d_in[0];
    const int* ei = (const int*)d_in[1];
    const int nE = in_sizes[1] / 2;
    const int nN = NNODES;
    const int nTot = nE + nN;

    const float* W[3]    = {(const float*)d_in[2],  (const float*)d_in[8],  (const float*)d_in[14]};
    const float* ASRC[3] = {(const float*)d_in[3],  (const float*)d_in[9],  (const float*)d_in[15]};
    const float* ADST[3] = {(const float*)d_in[4],  (const float*)d_in[10], (const float*)d_in[16]};
    const float* BB[3]   = {(const float*)d_in[5],  (const float*)d_in[11], (const float*)d_in[17]};
    const float* SW[3]   = {(const float*)d_in[6],  (const float*)d_in[12], (const float*)d_in[18]};
    const float* SB[3]   = {(const float*)d_in[7],  (const float*)d_in[13], (const float*)d_in[19]};
    const int FIN[3] = {128, HC, HC};

    float *ph, *pacc, *px, *ps, *pd;
    int *pdeg, *pcur, *prp, *pcsr;
    __nv_bfloat16 *pbh, *pbl;
    cudaGetSymbolAddress((void**)&ph,   g_h);
    cudaGetSymbolAddress((void**)&pacc, g_acc);
    cudaGetSymbolAddress((void**)&px,   g_x);
    cudaGetSymbolAddress((void**)&ps,   g_s);
    cudaGetSymbolAddress((void**)&pd,   g_d);
    cudaGetSymbolAddress((void**)&pdeg, g_deg);
    cudaGetSymbolAddress((void**)&pcur, g_cur);
    cudaGetSymbolAddress((void**)&prp,  g_rp);
    cudaGetSymbolAddress((void**)&pcsr, g_csr);
    cudaGetSymbolAddress((void**)&pbh,  g_bh);
    cudaGetSymbolAddress((void**)&pbl,  g_bl);

    // ---- weight preconvert: fused [512,K] bf16 hi/lo per layer ----
    for (int l = 0; l < 3; l++) {
        const int K = FIN[l];
        const int nb = (K * 256 + 255) / 256;
        __nv_bfloat16* bh = pbh + (size_t)l * 131072;
        __nv_bfloat16* bl = pbl + (size_t)l * 131072;
        conv_w_kernel<<<nb, 256>>>(W[l],  bh, bl, K, 0);
        conv_w_kernel<<<nb, 256>>>(SW[l], bh, bl, K, 256);
    }

    // ---- CSR build (once; reused by all 3 layers) ----
    cudaMemsetAsync(pdeg, 0, NNODES * sizeof(int));
    const int eBlocks = (nTot + 255) / 256;
    hist_kernel<<<eBlocks, 256>>>(ei, pdeg, nE, nTot);
    scan_kernel<<<1, 1024>>>(pdeg, prp, pcur, nN);
    scatter_kernel<<<eBlocks, 256>>>(ei, pcur, pcsr, nE, nTot);

    const dim3 gemmGrid(4, (nN + 127) / 128);
    const int sdBlocks  = (nN * 32 + 255) / 256;
    const int aggBlocks = (nN * 32 + 255) / 256;

    const float* xin = x0;
    for (int l = 0; l < 3; l++) {
        const int K = FIN[l];
        __nv_bfloat16* bh = pbh + (size_t)l * 131072;
        __nv_bfloat16* bl = pbl + (size_t)l * 131072;
        gemm_mma_kernel<<<gemmGrid, 256>>>(xin, bh, bl, ph, pacc,
                                           BB[l], SB[l], nN, K);
        compute_sd_kernel<<<sdBlocks, 256>>>(ph, ASRC[l], ADST[l], ps, pd, nN);
        float* xout = (l == 2) ? (float*)d_out : px;
        node_agg_kernel<<<aggBlocks, 256>>>(prp, pcsr, ps, pd, ph, pacc, xout, nN);
        xin = px;
    }
}